// round 14
// baseline (speedup 1.0000x reference)
#include <cuda_runtime.h>
#include <cuda_fp16.h>
#include <mma.h>
#include <cstdint>

using namespace nvcuda;

// Problem dims
#define BATCH 256
#define J_DIM 1024            // neurons (reduction of GEMM1)
#define K_DIM 1024            // n_feat  (M of GEMM1)
#define L_DIM 256             // in_dim
#define M_DIM 128             // out_dim (N of GEMM2)
#define LM    (L_DIM * M_DIM) // 32768   (N of GEMM1)
#define R_DIM (K_DIM * L_DIM) // 262144  (reduction of GEMM2)

// GEMM2 tiling (pipelined, fp16 X from g_X16)
#define BM 128
#define BK2 32
#define LDX2 40                         // halves per X row (80 B, conflict-free)
#define LDE2 136                        // halves per E row (272 B)
#define X2_BYTES (BM * LDX2 * 2)        // 10240
#define E2_BYTES (BK2 * LDE2 * 2)       // 8704
#define STG2 (X2_BYTES + E2_BYTES)      // 18944
#define NST2 3
#define SMEM2 (NST2 * STG2)             // 56832 (x2 CTAs = 114KB <= 228KB)
#define NSPLIT 128
#define SPLIT_LEN (R_DIM / NSPLIT)      // 2048
#define NCH2 (SPLIT_LEN / BK2)          // 64

// GEMM1 tiling: CTA 128x128x64, 4 warps of 64x64, 128 threads, 2 CTAs/SM
#define BM1 128
#define BN1 128
#define BK1 64
#define T1_THREADS 128
#define LDA1 72                        // halves (144 B rows)
#define LDB1 136                       // halves (272 B rows)
#define NST1 3
#define A1_BYTES (BM1 * LDA1 * 2)      // 18432
#define B1_BYTES (BK1 * LDB1 * 2)      // 17408
#define STG1 (A1_BYTES + B1_BYTES)     // 35840
#define SMEM1 (NST1 * STG1)            // 107520 (x2 CTAs = 215KB <= 228KB)
#define NCH1 (J_DIM / BK1)             // 16

// Fused grid: even blocks convert X (+ zero out), odd blocks do GEMM1
#define N_CONV_BLK 2048
#define X_UNITS (((size_t)BATCH * R_DIM) / 4)   // 16777216 float4 units
#define UNITS_PER_CONV (X_UNITS / N_CONV_BLK)   // 8192
#define ZERO_BLKS 16
#define ZERO_PER_BLK ((BATCH * M_DIM) / ZERO_BLKS)  // 2048

// Scratch (static device globals — no allocation APIs allowed)
__device__ __half g_GT[(size_t)K_DIM * J_DIM];   //   2 MB : G^T fp16, (k, j)
__device__ __half g_D16[(size_t)J_DIM * LM];     //  64 MB : (v-w) fp16, (j, lm)
__device__ __half g_E[(size_t)K_DIM * LM];       //  64 MB : E fp16, (r, m)
__device__ __half g_X16[(size_t)BATCH * R_DIM];  // 134 MB : x fp16, (i, r)

// ---------------------------------------------------------------------------
// Helpers
// ---------------------------------------------------------------------------
__device__ __forceinline__ uint32_t smem_u32(const void* p) {
    uint32_t a;
    asm("{ .reg .u64 t; cvta.to.shared.u64 t, %1; cvt.u32.u64 %0, t; }" : "=r"(a) : "l"(p));
    return a;
}
#define CP_ASYNC16(dst, src) \
    asm volatile("cp.async.cg.shared.global [%0], [%1], 16;" :: "r"(dst), "l"(src))
#define CP_COMMIT() asm volatile("cp.async.commit_group;" ::: "memory")
#define CP_WAIT(n)  asm volatile("cp.async.wait_group %0;" :: "n"(n) : "memory")

// ---------------------------------------------------------------------------
// Convert kernels
// ---------------------------------------------------------------------------

// G (j,k) fp32 -> g_GT (k,j) fp16
__global__ void conv_GT_kernel(const float* __restrict__ G) {
    __shared__ float t[32][33];
    int jx = blockIdx.y * 32 + threadIdx.y;
    int kx = blockIdx.x * 32 + threadIdx.x;
    t[threadIdx.y][threadIdx.x] = G[jx * K_DIM + kx];
    __syncthreads();
    int ko = blockIdx.x * 32 + threadIdx.y;
    int jo = blockIdx.y * 32 + threadIdx.x;
    g_GT[(size_t)ko * J_DIM + jo] = __float2half(t[threadIdx.x][threadIdx.y]);
}

// g_D16 = fp16(v - w), elementwise, 4 elems/thread (streaming, coalesced)
__global__ void conv_D_kernel(const float* __restrict__ v, const float* __restrict__ w) {
    size_t i = (size_t)blockIdx.x * blockDim.x + threadIdx.x;  // float4 units
    float4 a = reinterpret_cast<const float4*>(v)[i];
    float4 b = reinterpret_cast<const float4*>(w)[i];
    __half2 lo = __floats2half2_rn(a.x - b.x, a.y - b.y);
    __half2 hi = __floats2half2_rn(a.z - b.z, a.w - b.w);
    __half2* dst = reinterpret_cast<__half2*>(&g_D16[i * 4]);
    dst[0] = lo;
    dst[1] = hi;
}

// ---------------------------------------------------------------------------
// GEMM1 fused: odd blocks run the 128x128x64 WMMA GEMM (E = GT * D16),
// even blocks convert X fp32 -> g_X16 fp16 (and the first 16 zero `out`),
// riding in GEMM1's idle DRAM bandwidth. grid = 4096 x 128 threads.
// ---------------------------------------------------------------------------
__global__ __launch_bounds__(T1_THREADS, 2) void gemm1_fused(const float* __restrict__ X,
                                                             float* __restrict__ out) {
    const int L = blockIdx.x;
    const int tid = threadIdx.x;

    if (!(L & 1)) {
        // ---- conv-X block (+ zero) ----
        const int c = L >> 1;               // 0..2047
        const float4* xs = reinterpret_cast<const float4*>(X);
        __half2* dst = reinterpret_cast<__half2*>(g_X16);
        size_t base = (size_t)c * UNITS_PER_CONV;
#pragma unroll 4
        for (int k = 0; k < (int)(UNITS_PER_CONV / T1_THREADS); k++) {
            size_t idx = base + (size_t)k * T1_THREADS + tid;
            float4 a = xs[idx];
            dst[idx * 2]     = __floats2half2_rn(a.x, a.y);
            dst[idx * 2 + 1] = __floats2half2_rn(a.z, a.w);
        }
        if (c < ZERO_BLKS) {
#pragma unroll
            for (int k = 0; k < ZERO_PER_BLK / T1_THREADS; k++)
                out[c * ZERO_PER_BLK + k * T1_THREADS + tid] = 0.0f;
        }
        return;
    }

    // ---- GEMM1 block ----
    extern __shared__ char sm[];
    const int g    = L >> 1;              // 0..2047
    const int warp = tid >> 5;
    const int lane = tid & 31;
    const int wm   = warp >> 1;   // 0..1  (64-row slab)
    const int wn   = warp & 1;    // 0..1  (64-col slab)
    const int mBase = (g & 7) * BM1;
    const int nBase = (g >> 3) * BN1;

    const uint32_t smem_base = smem_u32(sm);

    wmma::fragment<wmma::accumulator, 16, 16, 16, float> acc[4][4];
#pragma unroll
    for (int i = 0; i < 4; i++)
#pragma unroll
        for (int j = 0; j < 4; j++)
            wmma::fill_fragment(acc[i][j], 0.0f);

    auto fill = [&](int s, int chunk) {
        uint32_t a_base = smem_base + s * STG1;
        uint32_t b_base = a_base + A1_BYTES;
#pragma unroll
        for (int u = tid; u < 1024; u += T1_THREADS) {
            int row = u >> 3, c = u & 7;
            uint32_t dst = a_base + row * (LDA1 * 2) + c * 16;
            const void* src = &g_GT[(size_t)(mBase + row) * J_DIM + chunk * BK1 + c * 8];
            CP_ASYNC16(dst, src);
        }
#pragma unroll
        for (int u = tid; u < 1024; u += T1_THREADS) {
            int row = u >> 4, c = u & 15;
            uint32_t dst = b_base + row * (LDB1 * 2) + c * 16;
            const void* src = &g_D16[(size_t)(chunk * BK1 + row) * LM + nBase + c * 8];
            CP_ASYNC16(dst, src);
        }
        CP_COMMIT();
    };

#pragma unroll
    for (int s = 0; s < NST1; s++) fill(s, s);

#pragma unroll 1
    for (int i = 0; i < NCH1; i++) {
        const int s = i % NST1;
        if (i < NCH1 - 1) CP_WAIT(1);
        else              CP_WAIT(0);
        __syncthreads();   // chunk i resident; all warps done with chunk i-1

        if (i >= 1 && i + 2 < NCH1)
            fill((i + 2) % NST1, i + 2);   // overwrite slot (i-1)%3, now free

        const __half* As = reinterpret_cast<const __half*>(sm + s * STG1);
        const __half* Bs = reinterpret_cast<const __half*>(sm + s * STG1 + A1_BYTES);

#pragma unroll
        for (int kk = 0; kk < BK1 / 16; kk++) {
            wmma::fragment<wmma::matrix_a, 16, 16, 16, __half, wmma::row_major> af[4];
            wmma::fragment<wmma::matrix_b, 16, 16, 16, __half, wmma::row_major> bf[4];
#pragma unroll
            for (int ii = 0; ii < 4; ii++)
                wmma::load_matrix_sync(af[ii],
                    &As[(wm * 64 + ii * 16) * LDA1 + kk * 16], LDA1);
#pragma unroll
            for (int j = 0; j < 4; j++)
                wmma::load_matrix_sync(bf[j],
                    &Bs[(kk * 16) * LDB1 + wn * 64 + j * 16], LDB1);
#pragma unroll
            for (int ii = 0; ii < 4; ii++)
#pragma unroll
                for (int j = 0; j < 4; j++)
                    wmma::mma_sync(acc[ii][j], af[ii], bf[j], acc[ii][j]);
        }
    }

    __syncthreads();   // smem free for epilogue staging

    float* stg = reinterpret_cast<float*>(sm) + warp * 256;
    const int r  = lane >> 1;
    const int c8 = (lane & 1) * 8;
#pragma unroll
    for (int i = 0; i < 4; i++)
#pragma unroll
        for (int j = 0; j < 4; j++) {
            wmma::store_matrix_sync(stg, acc[i][j], 16, wmma::mem_row_major);
            __syncwarp();
            const float* sp = &stg[r * 16 + c8];
            __half2 h[4];
#pragma unroll
            for (int p = 0; p < 4; p++)
                h[p] = __floats2half2_rn(sp[2 * p], sp[2 * p + 1]);
            size_t off = (size_t)(mBase + wm * 64 + i * 16 + r) * LM
                       + nBase + wn * 64 + j * 16 + c8;
            *reinterpret_cast<uint4*>(&g_E[off]) = *reinterpret_cast<uint4*>(h);
            __syncwarp();
        }
}

// ---------------------------------------------------------------------------
// GEMM2: out[i, m] += sum_r g_X16[i, r] * E[r, m]
// 3-stage cp.async pipeline, fp16 X (no convert phase, one barrier/chunk).
// grid (NSPLIT, BATCH/BM = 2), 256 threads (8 warps, 4x2 of 32x64).
// ---------------------------------------------------------------------------
__global__ __launch_bounds__(256, 2) void gemm2_kernel3(float* __restrict__ out) {
    extern __shared__ char sm[];

    const int tid  = threadIdx.x;
    const int warp = tid >> 5;
    const int lane = tid & 31;
    const int wm   = warp >> 1;   // 0..3  (32-row slab)
    const int wn   = warp & 1;    // 0..1  (64-col slab)
    const int mBase  = blockIdx.y * BM;
    const int kStart = blockIdx.x * SPLIT_LEN;

    const uint32_t smem_base = smem_u32(sm);

    wmma::fragment<wmma::accumulator, 16, 16, 16, float> acc[2][4];
#pragma unroll
    for (int i = 0; i < 2; i++)
#pragma unroll
        for (int j = 0; j < 4; j++)
            wmma::fill_fragment(acc[i][j], 0.0f);

    auto fill = [&](int s, int chunk) {
        uint32_t x_base = smem_base + s * STG2;
        uint32_t e_base = x_base + X2_BYTES;
        int k0 = kStart + chunk * BK2;
#pragma unroll
        for (int u = tid; u < 512; u += 256) {        // X16: 128 rows x 4 x 16B
            int row = u >> 2, c = u & 3;
            uint32_t dst = x_base + row * (LDX2 * 2) + c * 16;
            const void* src = &g_X16[(size_t)(mBase + row) * R_DIM + k0 + c * 8];
            CP_ASYNC16(dst, src);
        }
#pragma unroll
        for (int u = tid; u < 512; u += 256) {        // E: 32 rows x 16 x 16B
            int row = u >> 4, c = u & 15;
            uint32_t dst = e_base + row * (LDE2 * 2) + c * 16;
            const void* src = &g_E[(size_t)(k0 + row) * M_DIM + c * 8];
            CP_ASYNC16(dst, src);
        }
        CP_COMMIT();
    };

#pragma unroll
    for (int s = 0; s < NST2; s++) fill(s, s);

#pragma unroll 1
    for (int i = 0; i < NCH2; i++) {
        const int s = i % NST2;
        if (i < NCH2 - 1) CP_WAIT(1);
        else              CP_WAIT(0);
        __syncthreads();   // chunk i resident; prior iter fully consumed

        if (i >= 1 && i + 2 < NCH2)
            fill((i + 2) % NST2, i + 2);

        const __half* Xs = reinterpret_cast<const __half*>(sm + s * STG2);
        const __half* Bs = reinterpret_cast<const __half*>(sm + s * STG2 + X2_BYTES);
#pragma unroll
        for (int kk = 0; kk < BK2; kk += 16) {
            wmma::fragment<wmma::matrix_a, 16, 16, 16, __half, wmma::row_major> af[2];
            wmma::fragment<wmma::matrix_b, 16, 16, 16, __half, wmma::row_major> bf[4];
#pragma unroll
            for (int ii = 0; ii < 2; ii++)
                wmma::load_matrix_sync(af[ii], &Xs[(wm * 32 + ii * 16) * LDX2 + kk], LDX2);
#pragma unroll
            for (int j = 0; j < 4; j++)
                wmma::load_matrix_sync(bf[j], &Bs[kk * LDE2 + wn * 64 + j * 16], LDE2);
#pragma unroll
            for (int ii = 0; ii < 2; ii++)
#pragma unroll
                for (int j = 0; j < 4; j++)
                    wmma::mma_sync(acc[ii][j], af[ii], bf[j], acc[ii][j]);
        }
    }

    __syncthreads();   // smem free for epilogue staging

    float* stg = reinterpret_cast<float*>(sm) + warp * 256;
    const int r  = lane >> 1;
    const int c8 = (lane & 1) * 8;
#pragma unroll
    for (int i = 0; i < 2; i++)
#pragma unroll
        for (int j = 0; j < 4; j++) {
            wmma::store_matrix_sync(stg, acc[i][j], 16, wmma::mem_row_major);
            __syncwarp();
            const float* sp = &stg[r * 16 + c8];
            int gm = mBase + wm * 32 + i * 16 + r;
            int gn = wn * 64 + j * 16 + c8;
#pragma unroll
            for (int t = 0; t < 8; t++)
                atomicAdd(&out[gm * M_DIM + gn + t], sp[t]);
            __syncwarp();
        }
}

// ---------------------------------------------------------------------------
// Launch
// ---------------------------------------------------------------------------
extern "C" void kernel_launch(void* const* d_in, const int* in_sizes, int n_in,
                              void* d_out, int out_size) {
    const float* x = (const float*)d_in[0];   // (256, 1024, 256)
    const float* G = (const float*)d_in[1];   // (1024, 1024)
    const float* v = (const float*)d_in[2];   // (1024, 256, 128)
    const float* w = (const float*)d_in[3];   // (1024, 256, 128)
    float* out = (float*)d_out;               // (256, 128)

    // Idempotent, non-stream API calls: capture-legal, no static guards.
    cudaFuncSetAttribute(gemm1_fused,
                         cudaFuncAttributeMaxDynamicSharedMemorySize, SMEM1);
    cudaFuncSetAttribute(gemm2_kernel3,
                         cudaFuncAttributeMaxDynamicSharedMemorySize, SMEM2);

    conv_GT_kernel<<<dim3(32, 32), dim3(32, 32)>>>(G);
    conv_D_kernel<<<(J_DIM * (size_t)LM) / (4 * 256), 256>>>(v, w);
    // 4096 blocks: odd = 2048 GEMM1 tiles, even = 2048 X-convert (+zero) blocks
    gemm1_fused<<<2 * N_CONV_BLK, T1_THREADS, SMEM1>>>(x, out);
    gemm2_kernel3<<<dim3(NSPLIT, BATCH / BM), 256, SMEM2>>>(out);
}